// round 17
// baseline (speedup 1.0000x reference)
#include <cuda_runtime.h>
#include <cuda_bf16.h>

// ---------------------------------------------------------------------------
// MLP_TI_Gram, single self-contained kernel. 32 CTAs x 1024 threads, TWO
// batch pairs per CTA (4 batches), zero cross-CTA communication.
// SIMD-f32x2 FFT: each batch pair packed lane-wise; 4 forward SIMD FFTs in
// 4 decoupled 256-thread named-barrier domains; the 2 packed inverses
// (u = P_b0 + i*P_b1) run in PARALLEL (one per pair). c stays in smem.
// gemm1 streams W1 from L2 (both pairs share lines -> L1 hits), mlp23 tail
// uses warp shuffles + per-pair barriers.
// ---------------------------------------------------------------------------

#define BATCH 128
#define NSEQ  1024
#define HID   128

typedef unsigned long long u64;

// ---- f32x2 packed helpers (Blackwell, PTX-only) ---------------------------
__device__ __forceinline__ u64 pk2(float lo, float hi) {
    u64 r;
    asm("mov.b64 %0, {%1,%2};" : "=l"(r) : "f"(lo), "f"(hi));
    return r;
}
__device__ __forceinline__ void upk2(u64 v, float& lo, float& hi) {
    asm("mov.b64 {%0,%1}, %2;" : "=f"(lo), "=f"(hi) : "l"(v));
}
__device__ __forceinline__ u64 fma2(u64 a, u64 b, u64 c) {
    u64 d;
    asm("fma.rn.f32x2 %0, %1, %2, %3;" : "=l"(d) : "l"(a), "l"(b), "l"(c));
    return d;
}
__device__ __forceinline__ u64 add2(u64 a, u64 b) {
    u64 d;
    asm("add.rn.f32x2 %0, %1, %2;" : "=l"(d) : "l"(a), "l"(b));
    return d;
}
__device__ __forceinline__ u64 mul2(u64 a, u64 b) {
    u64 d;
    asm("mul.rn.f32x2 %0, %1, %2;" : "=l"(d) : "l"(a), "l"(b));
    return d;
}

__device__ __forceinline__ float celu1(float v) {
    return v > 0.0f ? v : expm1f(v);
}
__device__ __forceinline__ float2 cmul(float2 a, float2 b) {
    return make_float2(a.x * b.x - a.y * b.y, a.x * b.y + a.y * b.x);
}
__device__ __forceinline__ void barx(int id, int cnt) {
    asm volatile("bar.sync %0, %1;" :: "r"(id), "r"(cnt) : "memory");
}

// SIMD complex multiply: (Rb,Ib) = (Ra,Ia) * w, both lanes by scalar w.
#define SCMUL(Rb, Ib, Ra, Ia, wx2, wy2, wyn2) do { \
    (Rb) = fma2((Ia), (wyn2), mul2((Ra), (wx2))); \
    (Ib) = fma2((Ia), (wx2),  mul2((Ra), (wy2))); \
} while (0)

// ---------------------------------------------------------------------------
// Dynamic smem (u64 units). Per pair p (p = 0,1), base pb = p*8192:
//   signal s (0: ch01, 1: ch2) at pb + s*4096: RA|IA|RB|IB (1024 each)
// tw float2[768] at u64 16384..17151.
// Overlays per pair (after producers dead):
//   inverse ping-pong: bufX = (float2*)(pb+2048), bufY = (float2*)(pb+3072)
//   c2  -> pb+6144..7167 (signal1 RB)
//   part[16][128] -> pb+0..2047 ; red2[4][128] -> pb+2048..2559
//   h1s float[256] -> pb+2560..2591 ; s2u[4][128] -> pb+2816..3327
//   prb[4] -> pb+3328
// ---------------------------------------------------------------------------
#define SMEM_BYTES (17152 * 8)

__global__ __launch_bounds__(1024, 1)
void fused_all(const float* __restrict__ x,
               const float* __restrict__ W1, const float* __restrict__ b1,
               const float* __restrict__ W2, const float* __restrict__ b2,
               const float* __restrict__ W3, const float* __restrict__ b3,
               float* __restrict__ out) {
    extern __shared__ char dsm_raw[];
    u64* sm = (u64*)dsm_raw;
    float2* tw = (float2*)(sm + 16384);

    const int t  = threadIdx.x;
    const int pg = t >> 9;              // pair group 0/1
    const int g  = (t >> 8) & 1;        // signal within pair
    const int G  = t >> 8;              // global group 0..3
    const int i  = t & 255;
    const int tt = t & 511;

    const int B0 = blockIdx.x * 4 + pg * 2;
    const float* __restrict__ xb0 = x + (size_t)B0 * NSEQ * 3;
    const float* __restrict__ xb1 = xb0 + NSEQ * 3;

    const u64 M1   = pk2(-1.0f, -1.0f);
    const u64 HALF = pk2(0.5f, 0.5f);
#define sub2(a, b) fma2((b), M1, (a))

    u64* base = sm + pg * 8192;
    u64* mRA  = base + g * 4096;
    u64* mIA  = mRA + 1024;
    u64* mRB  = mRA + 2048;
    u64* mIB  = mRA + 3072;

    // twiddle table: tw[m] = exp(-2*pi*i*m/1024), m in [0,768)
    if (t < 768) {
        float s_, c_;
        sincospif(-(float)t * (1.0f / 512.0f), &s_, &c_);
        tw[t] = make_float2(c_, s_);
    }

    // ---- forward stage 0 (w=1): load x pair directly from gmem ----
    {
        u64 Ra[4], Ia[4];
#pragma unroll
        for (int r = 0; r < 4; r++) {
            int j3 = 3 * (i + 256 * r);
            if (g == 0) {
                Ra[r] = pk2(xb0[j3],     xb1[j3]);
                Ia[r] = pk2(xb0[j3 + 1], xb1[j3 + 1]);
            } else {
                Ra[r] = pk2(xb0[j3 + 2], xb1[j3 + 2]);
                Ia[r] = 0ull;
            }
        }
        u64 t02pR = add2(Ra[0], Ra[2]), t02pI = add2(Ia[0], Ia[2]);
        u64 t02mR = sub2(Ra[0], Ra[2]), t02mI = sub2(Ia[0], Ia[2]);
        u64 t13pR = add2(Ra[1], Ra[3]), t13pI = add2(Ia[1], Ia[3]);
        u64 t13mR = sub2(Ra[1], Ra[3]), t13mI = sub2(Ia[1], Ia[3]);
        const int d = i << 2;
        mRA[d]     = add2(t02pR, t13pR);  mIA[d]     = add2(t02pI, t13pI);
        mRA[d + 1] = add2(t02mR, t13mI);  mIA[d + 1] = sub2(t02mI, t13mR);
        mRA[d + 2] = sub2(t02pR, t13pR);  mIA[d + 2] = sub2(t02pI, t13pI);
        mRA[d + 3] = sub2(t02mR, t13mI);  mIA[d + 3] = add2(t02mI, t13mR);
    }
    __syncthreads();   // covers tw init + all groups' stage 0

    // ---- forward stages 1..3 (group-local barriers) ----
    {
        u64 *sR = mRA, *sI = mIA, *dR = mRB, *dI = mIB;
#pragma unroll
        for (int s = 1; s < 4; s++) {
            const int L = 1 << (2 * s);
            const int q = i & (L - 1);
            const int d = ((i >> (2 * s)) << (2 * s + 2)) | q;
            const int mi = q << (8 - 2 * s);
            const float2 w1 = tw[mi];
            const float2 w2 = tw[2 * mi];
            const float2 w3 = tw[3 * mi];
            const u64 w1x = pk2(w1.x, w1.x), w1y = pk2(w1.y, w1.y), w1n = pk2(-w1.y, -w1.y);
            const u64 w2x = pk2(w2.x, w2.x), w2y = pk2(w2.y, w2.y), w2n = pk2(-w2.y, -w2.y);
            const u64 w3x = pk2(w3.x, w3.x), w3y = pk2(w3.y, w3.y), w3n = pk2(-w3.y, -w3.y);

            u64 Ra0 = sR[i],       Ia0 = sI[i];
            u64 Ra1 = sR[i + 256], Ia1 = sI[i + 256];
            u64 Ra2 = sR[i + 512], Ia2 = sI[i + 512];
            u64 Ra3 = sR[i + 768], Ia3 = sI[i + 768];
            u64 Rb1, Ib1, Rb2, Ib2, Rb3, Ib3;
            SCMUL(Rb1, Ib1, Ra1, Ia1, w1x, w1y, w1n);
            SCMUL(Rb2, Ib2, Ra2, Ia2, w2x, w2y, w2n);
            SCMUL(Rb3, Ib3, Ra3, Ia3, w3x, w3y, w3n);

            u64 t02pR = add2(Ra0, Rb2), t02pI = add2(Ia0, Ib2);
            u64 t02mR = sub2(Ra0, Rb2), t02mI = sub2(Ia0, Ib2);
            u64 t13pR = add2(Rb1, Rb3), t13pI = add2(Ib1, Ib3);
            u64 t13mR = sub2(Rb1, Rb3), t13mI = sub2(Ib1, Ib3);

            dR[d]         = add2(t02pR, t13pR);  dI[d]         = add2(t02pI, t13pI);
            dR[d + L]     = add2(t02mR, t13mI);  dI[d + L]     = sub2(t02mI, t13mR);
            dR[d + 2 * L] = sub2(t02pR, t13pR);  dI[d + 2 * L] = sub2(t02pI, t13pI);
            dR[d + 3 * L] = sub2(t02mR, t13mI);  dI[d + 3 * L] = add2(t02mI, t13mR);

            u64* tmp;
            tmp = sR; sR = dR; dR = tmp;
            tmp = sI; sI = dI; dI = tmp;
            barx(1 + G, 256);
        }
    }
    // stage-3 output in B arrays

    // ---- forward stage 4: spectra into A arrays, then PAIR join ----
    {
        const float2 w1 = tw[i];
        const float2 w2 = tw[2 * i];
        const float2 w3 = tw[3 * i];
        const u64 w1x = pk2(w1.x, w1.x), w1y = pk2(w1.y, w1.y), w1n = pk2(-w1.y, -w1.y);
        const u64 w2x = pk2(w2.x, w2.x), w2y = pk2(w2.y, w2.y), w2n = pk2(-w2.y, -w2.y);
        const u64 w3x = pk2(w3.x, w3.x), w3y = pk2(w3.y, w3.y), w3n = pk2(-w3.y, -w3.y);

        u64 Ra0 = mRB[i],       Ia0 = mIB[i];
        u64 Ra1 = mRB[i + 256], Ia1 = mIB[i + 256];
        u64 Ra2 = mRB[i + 512], Ia2 = mIB[i + 512];
        u64 Ra3 = mRB[i + 768], Ia3 = mIB[i + 768];
        u64 Rb1, Ib1, Rb2, Ib2, Rb3, Ib3;
        SCMUL(Rb1, Ib1, Ra1, Ia1, w1x, w1y, w1n);
        SCMUL(Rb2, Ib2, Ra2, Ia2, w2x, w2y, w2n);
        SCMUL(Rb3, Ib3, Ra3, Ia3, w3x, w3y, w3n);

        u64 t02pR = add2(Ra0, Rb2), t02pI = add2(Ia0, Ib2);
        u64 t02mR = sub2(Ra0, Rb2), t02mI = sub2(Ia0, Ib2);
        u64 t13pR = add2(Rb1, Rb3), t13pI = add2(Ib1, Ib3);
        u64 t13mR = sub2(Rb1, Rb3), t13mI = sub2(Ib1, Ib3);

        mRA[i]       = add2(t02pR, t13pR);  mIA[i]       = add2(t02pI, t13pI);
        mRA[i + 256] = add2(t02mR, t13mI);  mIA[i + 256] = sub2(t02mI, t13mR);
        mRA[i + 512] = sub2(t02pR, t13pR);  mIA[i + 512] = sub2(t02pI, t13pI);
        mRA[i + 768] = sub2(t02mR, t13mI);  mIA[i + 768] = add2(t02mI, t13mR);
    }
    barx(5 + pg, 512);   // pair join: both signals' spectra ready

    u64* c2 = base + 6144;
    if (g == 0) {
        // ---- inverse for this pair: u = P_b0 + i*P_b1, PS fused ----
        const u64* R01 = base;
        const u64* I01 = base + 1024;
        const u64* R2h = base + 4096;
        const u64* I2h = base + 5120;
        float2* bufX = (float2*)(base + 2048);
        float2* bufY = (float2*)(base + 3072);

        {
            float2 u[4];
#pragma unroll
            for (int r = 0; r < 4; r++) {
                int k = i + 256 * r;
                int m = (1024 - k) & 1023;
                u64 s1 = fma2(R01[k], R01[k], mul2(I01[k], I01[k]));
                s1 = add2(s1, fma2(R01[m], R01[m], mul2(I01[m], I01[m])));
                s1 = mul2(s1, HALF);
                s1 = add2(s1, fma2(R2h[k], R2h[k], mul2(I2h[k], I2h[k])));
                float P0, P1;
                upk2(s1, P0, P1);
                u[r] = make_float2(P0, P1);
            }
            float2 t02p = make_float2(u[0].x + u[2].x, u[0].y + u[2].y);
            float2 t02m = make_float2(u[0].x - u[2].x, u[0].y - u[2].y);
            float2 t13p = make_float2(u[1].x + u[3].x, u[1].y + u[3].y);
            float2 t13m = make_float2(u[1].x - u[3].x, u[1].y - u[3].y);
            const int d = i << 2;
            bufX[d]     = make_float2(t02p.x + t13p.x, t02p.y + t13p.y);
            bufX[d + 1] = make_float2(t02m.x + t13m.y, t02m.y - t13m.x);
            bufX[d + 2] = make_float2(t02p.x - t13p.x, t02p.y - t13p.y);
            bufX[d + 3] = make_float2(t02m.x - t13m.y, t02m.y + t13m.x);
        }
        barx(1 + 2 * pg, 256);

        float2* src = bufX;
        float2* dst = bufY;
#pragma unroll
        for (int s = 1; s < 4; s++) {
            const int L = 1 << (2 * s);
            const int q = i & (L - 1);
            const int d2 = ((i >> (2 * s)) << (2 * s + 2)) | q;
            const int mi = q << (8 - 2 * s);
            const float2 w1t = tw[mi];
            const float2 w2t = tw[2 * mi];
            const float2 w3t = tw[3 * mi];

            float2 a0 = src[i];
            float2 a1 = src[i + 256];
            float2 a2 = src[i + 512];
            float2 a3 = src[i + 768];
            float2 b1_ = cmul(a1, w1t);
            float2 b2_ = cmul(a2, w2t);
            float2 b3_ = cmul(a3, w3t);

            float2 t02p2 = make_float2(a0.x + b2_.x, a0.y + b2_.y);
            float2 t02m2 = make_float2(a0.x - b2_.x, a0.y - b2_.y);
            float2 t13p2 = make_float2(b1_.x + b3_.x, b1_.y + b3_.y);
            float2 t13m2 = make_float2(b1_.x - b3_.x, b1_.y - b3_.y);

            dst[d2]         = make_float2(t02p2.x + t13p2.x, t02p2.y + t13p2.y);
            dst[d2 + L]     = make_float2(t02m2.x + t13m2.y, t02m2.y - t13m2.x);
            dst[d2 + 2 * L] = make_float2(t02p2.x - t13p2.x, t02p2.y - t13p2.y);
            dst[d2 + 3 * L] = make_float2(t02m2.x - t13m2.y, t02m2.y + t13m2.x);

            float2* tmp = src; src = dst; dst = tmp;
            barx(1 + 2 * pg, 256);
        }
        // stage-3 output in bufY

        {
            const float2 w1t = tw[i];
            const float2 w2t = tw[2 * i];
            const float2 w3t = tw[3 * i];

            float2 a0 = bufY[i];
            float2 a1 = bufY[i + 256];
            float2 a2 = bufY[i + 512];
            float2 a3 = bufY[i + 768];
            float2 b1_ = cmul(a1, w1t);
            float2 b2_ = cmul(a2, w2t);
            float2 b3_ = cmul(a3, w3t);

            float2 t02p2 = make_float2(a0.x + b2_.x, a0.y + b2_.y);
            float2 t02m2 = make_float2(a0.x - b2_.x, a0.y - b2_.y);
            float2 t13p2 = make_float2(b1_.x + b3_.x, b1_.y + b3_.y);
            float2 t13m2 = make_float2(b1_.x - b3_.x, b1_.y - b3_.y);

            const float inv = 1.0f / (1024.0f * 1024.0f);
            c2[i] = pk2((t02p2.x + t13p2.x) * inv, (t02p2.y + t13p2.y) * inv);
            c2[i + 256] = pk2((t02m2.x + t13m2.y) * inv,
                              (t02m2.y - t13m2.x) * inv);
            c2[i + 512] = pk2((t02p2.x - t13p2.x) * inv,
                              (t02p2.y - t13p2.y) * inv);
            c2[i + 768] = pk2((t02m2.x - t13m2.y) * inv,
                              (t02m2.y + t13m2.x) * inv);
        }
    } else {
        // idle half: warm L2 with this CTA's W1/W2 slices (read-only hints)
        int idx = (pg << 8) + i;             // 0..511 over both pairs
        if (idx < 128) {
            const float* p = W1 + (size_t)blockIdx.x * 4096 + idx * 32;
            asm volatile("prefetch.global.L2 [%0];" :: "l"(p));
        } else if (idx < 144) {
            const float* p = W2 + (size_t)blockIdx.x * 512 + (idx - 128) * 32;
            asm volatile("prefetch.global.L2 [%0];" :: "l"(p));
        }
    }
    __syncthreads();   // c2 of both pairs ready

    // ================= phase 3: gemm1 (per pair, 512 threads) ==============
    u64* part = base;                    // [16][128]
    {
        const int h4 = tt & 31;
        const int jc = tt >> 5;          // [0,16), 64 j each
        const float4* __restrict__ W1v = (const float4*)W1;

        u64 a0 = 0ull, a1 = 0ull, a2 = 0ull, a3 = 0ull;
#pragma unroll 8
        for (int j = jc * 64; j < jc * 64 + 64; j++) {
            u64 cv = c2[j];
            float4 wv = W1v[(j << 5) + h4];
            a0 = fma2(cv, pk2(wv.x, wv.x), a0);
            a1 = fma2(cv, pk2(wv.y, wv.y), a1);
            a2 = fma2(cv, pk2(wv.z, wv.z), a2);
            a3 = fma2(cv, pk2(wv.w, wv.w), a3);
        }
        part[jc * 128 + h4 * 4 + 0] = a0;
        part[jc * 128 + h4 * 4 + 1] = a1;
        part[jc * 128 + h4 * 4 + 2] = a2;
        part[jc * 128 + h4 * 4 + 3] = a3;
    }
    barx(5 + pg, 512);

    u64*   red2 = base + 2048;           // [4][128]
    float* h1s  = (float*)(base + 2560); // [2][128]
    {
        const int h = tt & 127, q = tt >> 7;
        u64 s0 = add2(part[(q * 4 + 0) * 128 + h], part[(q * 4 + 1) * 128 + h]);
        u64 s1 = add2(part[(q * 4 + 2) * 128 + h], part[(q * 4 + 3) * 128 + h]);
        red2[q * 128 + h] = add2(s0, s1);
    }
    barx(5 + pg, 512);

    if (tt < 128) {
        u64 v = add2(add2(red2[tt], red2[128 + tt]),
                     add2(red2[256 + tt], red2[384 + tt]));
        float va, vb;
        upk2(v, va, vb);
        float bb = b1[tt];
        h1s[tt]       = celu1(va + bb);
        h1s[128 + tt] = celu1(vb + bb);
    }
    barx(5 + pg, 512);

    // ================= phase 4: mlp23 (per pair) =================
    u64* s2u = base + 2816;              // [4][128]
    u64* prb = base + 3328;              // [4]
    {
        const int h = tt & 127, kc = tt >> 7;
        float a0 = 0.f, a1 = 0.f;
#pragma unroll
        for (int k = kc * 32; k < kc * 32 + 32; k++) {
            float w = W2[k * HID + h];
            a0 += h1s[k] * w;
            a1 += h1s[128 + k] * w;
        }
        s2u[kc * 128 + h] = pk2(a0, a1);
    }
    barx(5 + pg, 512);

    if (tt < 128) {
        u64 v = add2(add2(s2u[tt], s2u[128 + tt]),
                     add2(s2u[256 + tt], s2u[384 + tt]));
        float va, vb;
        upk2(v, va, vb);
        float bb = b2[tt];
        float w3 = W3[tt];
        u64 rv = pk2(celu1(va + bb) * w3, celu1(vb + bb) * w3);
#pragma unroll
        for (int o = 16; o > 0; o >>= 1)
            rv = add2(rv, __shfl_down_sync(0xffffffffu, rv, o));
        if ((tt & 31) == 0) prb[tt >> 5] = rv;
    }
    barx(5 + pg, 512);

    if (tt == 0) {
        u64 v = add2(add2(prb[0], prb[1]), add2(prb[2], prb[3]));
        float ya, yb;
        upk2(v, ya, yb);
        float bb = b3[0];
        out[B0]     = ya + bb;
        out[B0 + 1] = yb + bb;
    }
#undef sub2
}

// ---------------------------------------------------------------------------
extern "C" void kernel_launch(void* const* d_in, const int* in_sizes, int n_in,
                              void* d_out, int out_size) {
    const float* x  = (const float*)d_in[0];
    const float* W1 = (const float*)d_in[1];
    const float* b1 = (const float*)d_in[2];
    const float* W2 = (const float*)d_in[3];
    const float* b2 = (const float*)d_in[4];
    const float* W3 = (const float*)d_in[5];
    const float* b3 = (const float*)d_in[6];
    float* out = (float*)d_out;

    static int configured = 0;
    if (!configured) {
        cudaFuncSetAttribute(fused_all,
                             cudaFuncAttributeMaxDynamicSharedMemorySize,
                             SMEM_BYTES);
        configured = 1;
    }

    fused_all<<<BATCH / 4, 1024, SMEM_BYTES>>>(x, W1, b1, W2, b2, W3, b3, out);
}